// round 9
// baseline (speedup 1.0000x reference)
#include <cuda_runtime.h>
#include <cuda_fp16.h>
#include <math.h>
#include <stdint.h>

#define BATCH 8
#define NPTS 4096
#define SPTS 1024
#define D1 128
#define D2 256
#define INCH 384
#define OUTCH 256
#define NTOT (BATCH * NPTS)   // 32768
#define BN_EPS 1e-5f
#define WTOT (OUTCH * INCH + 2 * OUTCH * OUTCH)   // 229376
#define NCTA 296              // 2 CTAs x 148 SMs, all resident
#define NJOBS 512             // 256 sample-blocks x 2 n-blocks

// ---------------- scratch (device globals; no allocs allowed) ----------------
__device__ __align__(256) __half g_X[(size_t)NTOT * INCH];
__device__ __align__(256) __half g_A1[(size_t)NTOT * OUTCH];
__device__ __align__(256) __half g_A2[(size_t)NTOT * OUTCH];
__device__ __align__(256) float g_Z[(size_t)NTOT * OUTCH];
__device__ __align__(256) __half g_Wh[WTOT];
__device__ __align__(256) __half g_Wl[WTOT];
__device__ float g_psum[3][OUTCH];
__device__ float g_psq[3][OUTCH];
__device__ unsigned g_bar;        // monotonic grid-barrier counter (zeroed by prep)
__device__ unsigned g_job[4];     // per-gemm-phase job counters (zeroed by prep)

// ---------------- smem layout ----------------
#define STAGE_SZ 24576
#define NSTAGE 4
#define SM_BIAS (NSTAGE * STAGE_SZ)     // 98304: 256 floats
#define SM_JOB  (SM_BIAS + 1024)        // 99328: 1 uint
#define MEGA_SMEM 99392

// ---------------- helpers ----------------
__device__ __forceinline__ uint32_t smem_to_u32(const void* p) {
    uint32_t a;
    asm("{ .reg .u64 t; cvta.to.shared.u64 t, %1; cvt.u32.u64 %0, t; }" : "=r"(a) : "l"(p));
    return a;
}
#define SZ64(o) ((o) ^ (((o) >> 3) & 0x30))
#define CP16(dst, src) \
    asm volatile("cp.async.cg.shared.global [%0], [%1], 16;" :: "r"(dst), "l"(src) : "memory")
template <int N>
__device__ __forceinline__ void cp_wait() {
    asm volatile("cp.async.wait_group %0;" :: "n"(N) : "memory");
}
__device__ __forceinline__ void ldsm_x4(uint32_t& r0, uint32_t& r1, uint32_t& r2, uint32_t& r3,
                                        uint32_t addr) {
    asm volatile("ldmatrix.sync.aligned.m8n8.x4.shared.b16 {%0,%1,%2,%3}, [%4];"
                 : "=r"(r0), "=r"(r1), "=r"(r2), "=r"(r3) : "r"(addr));
}
__device__ __forceinline__ void mma_fp16(float& c0, float& c1, float& c2, float& c3,
                                         uint32_t a0, uint32_t a1, uint32_t a2, uint32_t a3,
                                         uint32_t b0, uint32_t b1) {
    asm volatile("mma.sync.aligned.m16n8k16.row.col.f32.f16.f16.f32 "
                 "{%0,%1,%2,%3}, {%4,%5,%6,%7}, {%8,%9}, {%0,%1,%2,%3};"
                 : "+f"(c0), "+f"(c1), "+f"(c2), "+f"(c3)
                 : "r"(a0), "r"(a1), "r"(a2), "r"(a3), "r"(b0), "r"(b1));
}
__device__ __forceinline__ float gelu_exact(float x) {
    return 0.5f * x * (1.0f + erff(x * 0.70710678118654752f));
}

// grid barrier: monotonic counter, target = phase * NCTA
__device__ __forceinline__ void gbar(int phase) {
    __syncthreads();
    if (threadIdx.x == 0) {
        __threadfence();
        atomicAdd(&g_bar, 1u);
        const unsigned target = (unsigned)(phase * NCTA);
        unsigned v;
        do {
            asm volatile("ld.global.acquire.gpu.b32 %0, [%1];" : "=r"(v) : "l"(&g_bar));
            if (v < target) __nanosleep(64);
        } while (v < target);
    }
    __syncthreads();
}

// ---------------- prep kernel: weight split + zero counters/stats ----------------
__global__ __launch_bounds__(256) void prep_kernel(
    const float* __restrict__ Wf, const float* __restrict__ W1, const float* __restrict__ W2)
{
    int i = blockIdx.x * 256 + threadIdx.x;
    if (i == 0) g_bar = 0;
    if (i < 4) g_job[i] = 0;
    if (i < 3 * OUTCH) { (&g_psum[0][0])[i] = 0.0f; (&g_psq[0][0])[i] = 0.0f; }
    if (i >= WTOT) return;
    float w;
    if (i < OUTCH * INCH)                      w = Wf[i];
    else if (i < OUTCH * INCH + OUTCH * OUTCH) w = W1[i - OUTCH * INCH];
    else                                       w = W2[i - OUTCH * INCH - OUTCH * OUTCH];
    __half h = __float2half_rn(w);
    g_Wh[i] = h;
    g_Wl[i] = __float2half_rn(w - __half2float(h));
}

// ---------------- phase: topk + build fused input (CTAs 0..127, 256 samples each) ----------------
__device__ void topk_build_phase(char* smem,
    const float* __restrict__ xyz1, const float* __restrict__ xyz2,
    const float* __restrict__ points1, const float* __restrict__ points2)
{
    const int job = blockIdx.x;        // 0..127
    if (job >= 128) return;
    const int tid = threadIdx.x;
    const int b = job >> 4;            // 16 jobs per batch
    const int s0 = (job & 15) * 256;   // sample offset within batch

    float4* q  = (float4*)smem;                      // 16KB
    float* sw  = (float*)(smem + 16384);             // 256*3 floats
    int*   sid = (int*)(smem + 16384 + 3072);        // 256*3 ints

    for (int s = tid; s < SPTS; s += 256) {
        const float* p = xyz2 + ((size_t)b * SPTS + s) * 3;
        float x = p[0], y = p[1], z = p[2];
        q[s] = make_float4(x, y, z, x * x + y * y + z * z);
    }
    __syncthreads();

    {
        const int n = s0 + tid;
        const float* p = xyz1 + ((size_t)b * NPTS + n) * 3;
        float px = p[0], py = p[1], pz = p[2];
        float rn = px * px + py * py + pz * pz;
        float d0 = 3.4e38f, d1 = 3.4e38f, d2 = 3.4e38f;
        int i0 = 0, i1 = 0, i2 = 0;
        #pragma unroll 4
        for (int s = 0; s < SPTS; s++) {
            float4 qq = q[s];
            float d = rn - 2.0f * (px * qq.x + py * qq.y + pz * qq.z) + qq.w;
            if (d < d2) {
                if (d < d1) {
                    if (d < d0) { d2 = d1; i2 = i1; d1 = d0; i1 = i0; d0 = d; i0 = s; }
                    else        { d2 = d1; i2 = i1; d1 = d;  i1 = s; }
                } else          { d2 = d;  i2 = s; }
            }
        }
        float r0 = 1.0f / (d0 + 1e-8f);
        float r1 = 1.0f / (d1 + 1e-8f);
        float r2 = 1.0f / (d2 + 1e-8f);
        float rs = 1.0f / (r0 + r1 + r2);
        sw[tid * 3 + 0] = r0 * rs;
        sw[tid * 3 + 1] = r1 * rs;
        sw[tid * 3 + 2] = r2 * rs;
        sid[tid * 3 + 0] = i0;
        sid[tid * 3 + 1] = i1;
        sid[tid * 3 + 2] = i2;
    }
    __syncthreads();

    // build: warp per sample, lanes over channels (coalesced)
    const int wid = tid >> 5, lane = tid & 31;
    const float* p2base = points2 + (size_t)b * SPTS * D2;
    for (int sIdx = wid; sIdx < 256; sIdx += 8) {
        const int sample = b * NPTS + s0 + sIdx;
        const float w0 = sw[sIdx * 3 + 0], w1 = sw[sIdx * 3 + 1], w2 = sw[sIdx * 3 + 2];
        const int   i0 = sid[sIdx * 3 + 0], i1 = sid[sIdx * 3 + 1], i2 = sid[sIdx * 3 + 2];
        const float* p1 = points1 + (size_t)sample * D1;
        #pragma unroll
        for (int it = 0; it < 12; it++) {
            const int c = it * 32 + lane;
            float v;
            if (c < D1) {
                v = __ldg(p1 + c);
            } else {
                const int cc = c - D1;
                v = w0 * __ldg(p2base + (size_t)i0 * D2 + cc)
                  + w1 * __ldg(p2base + (size_t)i1 * D2 + cc)
                  + w2 * __ldg(p2base + (size_t)i2 * D2 + cc);
            }
            g_X[(size_t)sample * INCH + c] = __float2half_rn(v);
        }
    }
}

// ---------------- phase: GEMM (job-stealing over 512 tiles) ----------------
__device__ __forceinline__ void load_tile32(uint32_t dst, const __half* src,
                                            int ldK, int row0, int k0, int tid) {
    #pragma unroll
    for (int j = 0; j < 2; j++) {
        int g = tid + j * 256;
        int r = g >> 2;
        int c16 = (g & 3) * 16;
        const char* s = (const char*)(src + (size_t)(row0 + r) * ldK + k0) + c16;
        CP16(dst + SZ64(r * 64 + c16), s);
    }
}

template <int K>
__device__ void gemm_phase(char* smem, const __half* __restrict__ X,
                           const float* __restrict__ bias, int woff, int layer,
                           unsigned* ctr)
{
    constexpr int NC = K / 32;
    const uint32_t sb = smem_to_u32(smem);
    const int tid = threadIdx.x;
    const int wid = tid >> 5;
    const int lane = tid & 31;

    float* sbias = (float*)(smem + SM_BIAS);
    unsigned* sjob = (unsigned*)(smem + SM_JOB);
    sbias[tid] = bias[tid];                      // full 256 channels
    __syncthreads();

    const __half* Wh = g_Wh + woff;
    const __half* Wl = g_Wl + woff;

    const int mWarp = (wid & 1) * 64;
    const int nWarp = (wid >> 1) * 32;
    const int aRow = mWarp + (lane & 15);
    const int aSel16 = (lane >> 4) * 16;
    const int bRow = nWarp + ((lane >> 4) << 3) + (lane & 7);
    const int bSel16 = ((lane >> 3) & 1) * 16;
    const int rr = lane >> 2;
    const int cc = (lane & 3) * 2;

    for (;;) {
        if (tid == 0) *sjob = atomicAdd(ctr, 1u);
        __syncthreads();
        const unsigned job = *sjob;
        if (job >= NJOBS) break;

        const int sample0 = (int)(job & 255) * 128;
        const int n0 = (int)(job >> 8) * 128;

        // prologue: chunks 0,1,2 into stages 0,1,2
        #pragma unroll
        for (int i = 0; i < 3; i++) {
            const uint32_t st = sb + i * STAGE_SZ;
            load_tile32(st,         X,  K, sample0, i * 32, tid);
            load_tile32(st + 8192,  Wh, K, n0,      i * 32, tid);
            load_tile32(st + 16384, Wl, K, n0,      i * 32, tid);
            asm volatile("cp.async.commit_group;" ::: "memory");
        }

        float acc[4][4][4];
        #pragma unroll
        for (int a = 0; a < 4; a++)
            #pragma unroll
            for (int b2 = 0; b2 < 4; b2++)
                #pragma unroll
                for (int c = 0; c < 4; c++) acc[a][b2][c] = 0.0f;

        for (int i = 0; i < NC; i++) {
            if (i <= NC - 3)      cp_wait<2>();
            else if (i == NC - 2) cp_wait<1>();
            else                  cp_wait<0>();
            __syncthreads();

            const uint32_t sA = sb + (i & 3) * STAGE_SZ;
            const uint32_t sBh = sA + 8192;
            const uint32_t sBl = sA + 16384;

            #pragma unroll
            for (int k16 = 0; k16 < 2; k16++) {
                uint32_t af[4][4];
                #pragma unroll
                for (int mb = 0; mb < 4; mb++) {
                    uint32_t addr = sA + SZ64((aRow + mb * 16) * 64 + k16 * 32 + aSel16);
                    ldsm_x4(af[mb][0], af[mb][1], af[mb][2], af[mb][3], addr);
                }
                uint32_t bh[2][4], bl[2][4];
                #pragma unroll
                for (int p = 0; p < 2; p++) {
                    uint32_t ah = sBh + SZ64((bRow + p * 16) * 64 + k16 * 32 + bSel16);
                    ldsm_x4(bh[p][0], bh[p][1], bh[p][2], bh[p][3], ah);
                    uint32_t al = sBl + SZ64((bRow + p * 16) * 64 + k16 * 32 + bSel16);
                    ldsm_x4(bl[p][0], bl[p][1], bl[p][2], bl[p][3], al);
                }
                #pragma unroll
                for (int mb = 0; mb < 4; mb++)
                    #pragma unroll
                    for (int nb = 0; nb < 4; nb++) {
                        uint32_t b0 = bh[nb >> 1][(nb & 1) * 2];
                        uint32_t b1 = bh[nb >> 1][(nb & 1) * 2 + 1];
                        mma_fp16(acc[mb][nb][0], acc[mb][nb][1], acc[mb][nb][2], acc[mb][nb][3],
                                 af[mb][0], af[mb][1], af[mb][2], af[mb][3], b0, b1);
                    }
                #pragma unroll
                for (int mb = 0; mb < 4; mb++)
                    #pragma unroll
                    for (int nb = 0; nb < 4; nb++) {
                        uint32_t b0 = bl[nb >> 1][(nb & 1) * 2];
                        uint32_t b1 = bl[nb >> 1][(nb & 1) * 2 + 1];
                        mma_fp16(acc[mb][nb][0], acc[mb][nb][1], acc[mb][nb][2], acc[mb][nb][3],
                                 af[mb][0], af[mb][1], af[mb][2], af[mb][3], b0, b1);
                    }
            }

            if (i + 3 < NC) {
                const int j = i + 3;
                const uint32_t st = sb + (j & 3) * STAGE_SZ;
                load_tile32(st,         X,  K, sample0, j * 32, tid);
                load_tile32(st + 8192,  Wh, K, n0,      j * 32, tid);
                load_tile32(st + 16384, Wl, K, n0,      j * 32, tid);
                asm volatile("cp.async.commit_group;" ::: "memory");
            }
        }

        // epilogue: bias, write Z (fp32, sample-major), fused BN partial sums
        #pragma unroll
        for (int nb = 0; nb < 4; nb++) {
            const int col = nWarp + nb * 8 + cc;
            const float b0 = sbias[n0 + col], b1 = sbias[n0 + col + 1];
            float cs0 = 0.0f, cs1 = 0.0f, cq0 = 0.0f, cq1 = 0.0f;
            #pragma unroll
            for (int mb = 0; mb < 4; mb++) {
                const int row0 = sample0 + mWarp + mb * 16 + rr;
                float v00 = acc[mb][nb][0] + b0;
                float v01 = acc[mb][nb][1] + b1;
                float v10 = acc[mb][nb][2] + b0;
                float v11 = acc[mb][nb][3] + b1;
                *(float2*)(g_Z + (size_t)row0 * OUTCH + n0 + col)       = make_float2(v00, v01);
                *(float2*)(g_Z + (size_t)(row0 + 8) * OUTCH + n0 + col) = make_float2(v10, v11);
                cs0 += v00 + v10;
                cs1 += v01 + v11;
                cq0 += v00 * v00 + v10 * v10;
                cq1 += v01 * v01 + v11 * v11;
            }
            #pragma unroll
            for (int off = 4; off <= 16; off <<= 1) {
                cs0 += __shfl_xor_sync(0xFFFFFFFF, cs0, off);
                cs1 += __shfl_xor_sync(0xFFFFFFFF, cs1, off);
                cq0 += __shfl_xor_sync(0xFFFFFFFF, cq0, off);
                cq1 += __shfl_xor_sync(0xFFFFFFFF, cq1, off);
            }
            if (lane < 4) {
                atomicAdd(&g_psum[layer][n0 + col],     cs0);
                atomicAdd(&g_psum[layer][n0 + col + 1], cs1);
                atomicAdd(&g_psq[layer][n0 + col],      cq0);
                atomicAdd(&g_psq[layer][n0 + col + 1],  cq1);
            }
        }
        __syncthreads();
    }
}

// ---------------- phase: BN finalize + GELU -> fp16 activation (grid-stride) ----------------
__device__ void bn_phase(char* smem, __half* __restrict__ A,
                         const float* __restrict__ gamma, const float* __restrict__ beta,
                         int layer)
{
    float* s_sc = (float*)smem;
    float* s_sh = s_sc + OUTCH;
    const int t = threadIdx.x;
    {
        float s = g_psum[layer][t];
        float q = g_psq[layer][t];
        float m = s * (1.0f / NTOT);
        float var = q * (1.0f / NTOT) - m * m;
        float r = rsqrtf(var + BN_EPS);
        float sc = r * __ldg(gamma + t);
        s_sc[t] = sc;
        s_sh[t] = __ldg(beta + t) - m * sc;
    }
    __syncthreads();

    const int total4 = OUTCH * NTOT / 4;
    for (int idx4 = blockIdx.x * 256 + t; idx4 < total4; idx4 += NCTA * 256) {
        const int c4 = (idx4 & 63) * 4;
        float4 z = ((const float4*)g_Z)[idx4];
        __half2 h01, h23;
        h01.x = __float2half_rn(gelu_exact(fmaf(z.x, s_sc[c4 + 0], s_sh[c4 + 0])));
        h01.y = __float2half_rn(gelu_exact(fmaf(z.y, s_sc[c4 + 1], s_sh[c4 + 1])));
        h23.x = __float2half_rn(gelu_exact(fmaf(z.z, s_sc[c4 + 2], s_sh[c4 + 2])));
        h23.y = __float2half_rn(gelu_exact(fmaf(z.w, s_sc[c4 + 3], s_sh[c4 + 3])));
        uint2 v;
        v.x = *reinterpret_cast<uint32_t*>(&h01);
        v.y = *reinterpret_cast<uint32_t*>(&h23);
        ((uint2*)A)[idx4] = v;
    }
}

// ---------------- phase: final BN + residual + GELU -> out ----------------
__device__ void final_phase(char* smem, float* __restrict__ out,
                            const float* __restrict__ gamma, const float* __restrict__ beta)
{
    float* s_sc = (float*)smem;
    float* s_sh = s_sc + OUTCH;
    const int t = threadIdx.x;
    {
        float s = g_psum[2][t];
        float q = g_psq[2][t];
        float m = s * (1.0f / NTOT);
        float var = q * (1.0f / NTOT) - m * m;
        float r = rsqrtf(var + BN_EPS);
        float sc = r * __ldg(gamma + t);
        s_sc[t] = sc;
        s_sh[t] = __ldg(beta + t) - m * sc;
    }
    __syncthreads();

    const int total4 = OUTCH * NTOT / 4;
    for (int idx4 = blockIdx.x * 256 + t; idx4 < total4; idx4 += NCTA * 256) {
        const int c4 = (idx4 & 63) * 4;
        float4 z = ((const float4*)g_Z)[idx4];
        uint2 rv = ((const uint2*)g_A1)[idx4];
        __half2 r01 = *reinterpret_cast<__half2*>(&rv.x);
        __half2 r23 = *reinterpret_cast<__half2*>(&rv.y);
        float4 o;
        o.x = gelu_exact(fmaf(z.x, s_sc[c4 + 0], s_sh[c4 + 0]) + __half2float(r01.x));
        o.y = gelu_exact(fmaf(z.y, s_sc[c4 + 1], s_sh[c4 + 1]) + __half2float(r01.y));
        o.z = gelu_exact(fmaf(z.z, s_sc[c4 + 2], s_sh[c4 + 2]) + __half2float(r23.x));
        o.w = gelu_exact(fmaf(z.w, s_sc[c4 + 3], s_sh[c4 + 3]) + __half2float(r23.y));
        ((float4*)out)[idx4] = o;
    }
}

// ---------------- the persistent megakernel ----------------
__global__ __launch_bounds__(256, 2) void mega_kernel(
    const float* __restrict__ xyz1, const float* __restrict__ xyz2,
    const float* __restrict__ points1, const float* __restrict__ points2,
    const float* __restrict__ b_fuse, const float* __restrict__ g_fuse, const float* __restrict__ bt_fuse,
    const float* __restrict__ b1, const float* __restrict__ g1, const float* __restrict__ bt1,
    const float* __restrict__ b2, const float* __restrict__ g2, const float* __restrict__ bt2,
    float* __restrict__ out)
{
    extern __shared__ char smem[];

    // phase 1: topk + build fused fp16 input (CTAs 0..127)
    topk_build_phase(smem, xyz1, xyz2, points1, points2);
    gbar(1);

    // layer fuse
    gemm_phase<INCH>(smem, g_X, b_fuse, 0, 0, &g_job[0]);
    gbar(2);
    bn_phase(smem, g_A1, g_fuse, bt_fuse, 0);
    gbar(3);

    // layer 1
    gemm_phase<OUTCH>(smem, g_A1, b1, OUTCH * INCH, 1, &g_job[1]);
    gbar(4);
    bn_phase(smem, g_A2, g1, bt1, 1);
    gbar(5);

    // layer 2 + residual + output
    gemm_phase<OUTCH>(smem, g_A2, b2, OUTCH * INCH + OUTCH * OUTCH, 2, &g_job[2]);
    gbar(6);
    final_phase(smem, out, g2, bt2);
}

// ---------------- launch ----------------
extern "C" void kernel_launch(void* const* d_in, const int* in_sizes, int n_in,
                              void* d_out, int out_size) {
    const float* xyz1    = (const float*)d_in[0];
    const float* xyz2    = (const float*)d_in[1];
    const float* points1 = (const float*)d_in[2];
    const float* points2 = (const float*)d_in[3];
    const float* W_fuse  = (const float*)d_in[4];
    const float* b_fuse  = (const float*)d_in[5];
    const float* g_fuse  = (const float*)d_in[6];
    const float* bt_fuse = (const float*)d_in[7];
    const float* W1      = (const float*)d_in[8];
    const float* b1      = (const float*)d_in[9];
    const float* g1      = (const float*)d_in[10];
    const float* bt1     = (const float*)d_in[11];
    const float* W2      = (const float*)d_in[12];
    const float* b2      = (const float*)d_in[13];
    const float* g2      = (const float*)d_in[14];
    const float* bt2     = (const float*)d_in[15];
    float* out = (float*)d_out;

    static bool configured = false;
    if (!configured) {
        cudaFuncSetAttribute(mega_kernel, cudaFuncAttributeMaxDynamicSharedMemorySize, MEGA_SMEM);
        configured = true;
    }

    prep_kernel<<<(WTOT + 255) / 256, 256>>>(W_fuse, W1, W2);
    mega_kernel<<<NCTA, 256, MEGA_SMEM>>>(
        xyz1, xyz2, points1, points2,
        b_fuse, g_fuse, bt_fuse, b1, g1, bt1, b2, g2, bt2, out);
}